// round 1
// baseline (speedup 1.0000x reference)
#include <cuda_runtime.h>
#include <cuda_bf16.h>
#include <math.h>

// Problem constants
#define Bq    2
#define Nq    8192
#define Kn    16
#define CINc  128
#define CRc   128
#define Dd    256
#define COUTc 256
#define EPSc  1e-5f
#define NEGc  0.2f

#define NPTS  (Bq * Nq)        // 16384 points

// Output layout (float32, concatenated):
// [xyz: 49152][out_feat: 4194304][ori_relative_feature: 2621440][neighbors_idx as float: 262144]
#define OFF_XYZ   0
#define SZ_XYZ    (Bq * Nq * 3)
#define OFF_OUT   (OFF_XYZ + SZ_XYZ)
#define SZ_OUT    (Bq * Nq * COUTc)
#define OFF_ORF   (OFF_OUT + SZ_OUT)
#define SZ_ORF    (Bq * Nq * Kn * 10)
#define OFF_IDX   (OFF_ORF + SZ_ORF)
#define SZ_IDX    (Bq * Nq * Kn)

// Fused (BN-folded) parameter scratch in device globals (no allocation allowed).
__device__ float d_relWf[10 * CRc];       // rel_W * relScale  (column-scaled)
__device__ float d_relB[CRc];             // (rel_b - rel_m)*A + rel_be
__device__ float d_outWf[Dd * COUTc];     // out_W * outScale
__device__ float d_outB[COUTc];
__device__ float d_scWf[CINc * COUTc];    // sc_W * scScale
__device__ float d_scB[COUTc];

// ---------------------------------------------------------------------------
// Setup: fold BN (inference) + linear bias into weight/bias.
// BN(lin + b) = lin*A + ((b - m)*A + be),  A = g * rsqrt(v + eps)
// ---------------------------------------------------------------------------
__global__ void fuse_params_kernel(
    const float* __restrict__ rel_W, const float* __restrict__ rel_b,
    const float* __restrict__ rel_g, const float* __restrict__ rel_be,
    const float* __restrict__ rel_m, const float* __restrict__ rel_v,
    const float* __restrict__ out_W, const float* __restrict__ out_b,
    const float* __restrict__ out_g, const float* __restrict__ out_be,
    const float* __restrict__ out_m, const float* __restrict__ out_v,
    const float* __restrict__ sc_W,  const float* __restrict__ sc_b,
    const float* __restrict__ sc_g,  const float* __restrict__ sc_be,
    const float* __restrict__ sc_m,  const float* __restrict__ sc_v)
{
    int t = blockIdx.x * blockDim.x + threadIdx.x;
    int stride = gridDim.x * blockDim.x;

    for (int i = t; i < 10 * CRc; i += stride) {
        int c = i & (CRc - 1);
        d_relWf[i] = rel_W[i] * rel_g[c] * rsqrtf(rel_v[c] + EPSc);
    }
    for (int i = t; i < Dd * COUTc; i += stride) {
        int c = i & (COUTc - 1);
        d_outWf[i] = out_W[i] * out_g[c] * rsqrtf(out_v[c] + EPSc);
    }
    for (int i = t; i < CINc * COUTc; i += stride) {
        int c = i & (COUTc - 1);
        d_scWf[i] = sc_W[i] * sc_g[c] * rsqrtf(sc_v[c] + EPSc);
    }
    for (int i = t; i < CRc; i += stride) {
        float A = rel_g[i] * rsqrtf(rel_v[i] + EPSc);
        d_relB[i] = (rel_b[i] - rel_m[i]) * A + rel_be[i];
    }
    for (int i = t; i < COUTc; i += stride) {
        float A = out_g[i] * rsqrtf(out_v[i] + EPSc);
        d_outB[i] = (out_b[i] - out_m[i]) * A + out_be[i];
    }
    for (int i = t; i < COUTc; i += stride) {
        float A = sc_g[i] * rsqrtf(sc_v[i] + EPSc);
        d_scB[i] = (sc_b[i] - sc_m[i]) * A + sc_be[i];
    }
}

// ---------------------------------------------------------------------------
// Passthrough copies
// ---------------------------------------------------------------------------
__global__ void copy_f4_kernel(const float4* __restrict__ src, float4* __restrict__ dst, int n4)
{
    int t = blockIdx.x * blockDim.x + threadIdx.x;
    int stride = gridDim.x * blockDim.x;
    for (int i = t; i < n4; i += stride) dst[i] = src[i];
}

__global__ void i2f_kernel(const int* __restrict__ src, float* __restrict__ dst, int n)
{
    int t = blockIdx.x * blockDim.x + threadIdx.x;
    int stride = gridDim.x * blockDim.x;
    for (int i = t; i < n; i += stride) dst[i] = (float)src[i];
}

// ---------------------------------------------------------------------------
// Main fused kernel: one block per point (b, n), 256 threads.
//  Phase 1: stage idx, orf, center-feature; gather neighbors + rel MLP -> feat_s[16][256]
//  Phase 2: logits[k][c] = feat_s[k,:] . attn_W[:,c] ; softmax over k; pooled[c]
//  Phase 3: main = pooled @ outWf + outB; sc = fcen @ scWf + scB; leaky(main+sc)
// ---------------------------------------------------------------------------
__global__ __launch_bounds__(256, 8)
void lfa_kernel(const float* __restrict__ feature,
                const float* __restrict__ orf,
                const int*   __restrict__ nidx,
                const float* __restrict__ attn_W,
                float*       __restrict__ out_feat)
{
    const int p   = blockIdx.x;            // point id 0..16383
    const int b   = p >> 13;               // / 8192
    const int n   = p & (Nq - 1);
    const int tid = threadIdx.x;           // 0..255

    __shared__ float feat_s[Kn * Dd];      // 16 x 256 (gathered | rel)
    __shared__ float orf_s[Kn * 10];       // 160
    __shared__ float fcen_s[CINc];         // 128
    __shared__ float pooled_s[Dd];         // 256
    __shared__ int   idx_s[Kn];

    // ---- Stage small per-point data ----
    if (tid < Kn)        idx_s[tid]  = nidx[p * Kn + tid];
    if (tid < Kn * 10)   orf_s[tid]  = orf[p * (Kn * 10) + tid];
    if (tid < CINc)      fcen_s[tid] = feature[(size_t)p * CINc + tid];
    __syncthreads();

    // ---- Gather neighbor features: 16 rows x 128 cols (float4: 16x32) ----
    const float* fbase = feature + (size_t)b * Nq * CINc;
    for (int i = tid; i < Kn * (CINc / 4); i += 256) {
        int k  = i >> 5;           // /32
        int c4 = i & 31;
        float4 v = *((const float4*)(fbase + (size_t)idx_s[k] * CINc) + c4);
        *(float4*)&feat_s[k * Dd + c4 * 4] = v;
    }

    // ---- rel MLP: Linear(10->128) + BN + leaky (BN folded into weights) ----
    for (int i = tid; i < Kn * CRc; i += 256) {
        int k = i >> 7;            // /128
        int c = i & (CRc - 1);
        float acc = d_relB[c];
        const float* o = &orf_s[k * 10];
        #pragma unroll
        for (int d = 0; d < 10; d++) acc += o[d] * d_relWf[d * CRc + c];
        acc = (acc >= 0.f) ? acc : NEGc * acc;
        feat_s[k * Dd + CINc + c] = acc;
    }
    __syncthreads();

    // ---- Logits: thread c computes logit[k][c] for all k ----
    float acc[Kn];
    #pragma unroll
    for (int k = 0; k < Kn; k++) acc[k] = 0.f;

    const float* aw = attn_W + tid;        // column c = tid, stride Dd
    #pragma unroll 2
    for (int d = 0; d < Dd; d += 4) {
        float w0 = aw[(d + 0) * Dd];
        float w1 = aw[(d + 1) * Dd];
        float w2 = aw[(d + 2) * Dd];
        float w3 = aw[(d + 3) * Dd];
        #pragma unroll
        for (int k = 0; k < Kn; k++) {
            float4 f = *(const float4*)&feat_s[k * Dd + d];
            acc[k] += f.x * w0;
            acc[k] += f.y * w1;
            acc[k] += f.z * w2;
            acc[k] += f.w * w3;
        }
    }

    // ---- Softmax over k (per channel) + attention pooling ----
    float mx = acc[0];
    #pragma unroll
    for (int k = 1; k < Kn; k++) mx = fmaxf(mx, acc[k]);
    float s = 0.f;
    #pragma unroll
    for (int k = 0; k < Kn; k++) { acc[k] = expf(acc[k] - mx); s += acc[k]; }
    float pooled = 0.f;
    #pragma unroll
    for (int k = 0; k < Kn; k++) pooled += acc[k] * feat_s[k * Dd + tid];
    pooled_s[tid] = pooled / s;
    __syncthreads();

    // ---- main = pooled @ outWf + outB (BN folded) ----
    float m = d_outB[tid];
    #pragma unroll 2
    for (int d = 0; d < Dd; d += 4) {
        float4 pv = *(const float4*)&pooled_s[d];
        m += pv.x * d_outWf[(d + 0) * COUTc + tid];
        m += pv.y * d_outWf[(d + 1) * COUTc + tid];
        m += pv.z * d_outWf[(d + 2) * COUTc + tid];
        m += pv.w * d_outWf[(d + 3) * COUTc + tid];
    }

    // ---- shortcut = fcen @ scWf + scB (BN folded) ----
    float sc = d_scB[tid];
    #pragma unroll 2
    for (int d = 0; d < CINc; d += 4) {
        float4 fv = *(const float4*)&fcen_s[d];
        sc += fv.x * d_scWf[(d + 0) * COUTc + tid];
        sc += fv.y * d_scWf[(d + 1) * COUTc + tid];
        sc += fv.z * d_scWf[(d + 2) * COUTc + tid];
        sc += fv.w * d_scWf[(d + 3) * COUTc + tid];
    }

    float o = m + sc;
    o = (o >= 0.f) ? o : NEGc * o;
    out_feat[(size_t)p * COUTc + tid] = o;
}

// ---------------------------------------------------------------------------
extern "C" void kernel_launch(void* const* d_in, const int* in_sizes, int n_in,
                              void* d_out, int out_size)
{
    const float* xyz     = (const float*)d_in[0];
    const float* feature = (const float*)d_in[1];
    const float* orf     = (const float*)d_in[2];
    const int*   nidx    = (const int*)  d_in[3];
    const float* rel_W   = (const float*)d_in[4];
    const float* rel_b   = (const float*)d_in[5];
    const float* rel_g   = (const float*)d_in[6];
    const float* rel_be  = (const float*)d_in[7];
    const float* rel_m   = (const float*)d_in[8];
    const float* rel_v   = (const float*)d_in[9];
    const float* attn_W  = (const float*)d_in[10];
    const float* out_W   = (const float*)d_in[11];
    const float* out_b   = (const float*)d_in[12];
    const float* out_g   = (const float*)d_in[13];
    const float* out_be  = (const float*)d_in[14];
    const float* out_m   = (const float*)d_in[15];
    const float* out_v   = (const float*)d_in[16];
    const float* sc_W    = (const float*)d_in[17];
    const float* sc_b    = (const float*)d_in[18];
    const float* sc_g    = (const float*)d_in[19];
    const float* sc_be   = (const float*)d_in[20];
    const float* sc_m    = (const float*)d_in[21];
    const float* sc_v    = (const float*)d_in[22];

    float* out = (float*)d_out;

    // 1) Fold BN params into weights/biases
    fuse_params_kernel<<<128, 256>>>(rel_W, rel_b, rel_g, rel_be, rel_m, rel_v,
                                     out_W, out_b, out_g, out_be, out_m, out_v,
                                     sc_W,  sc_b,  sc_g,  sc_be,  sc_m,  sc_v);

    // 2) Passthrough outputs
    copy_f4_kernel<<<64, 256>>>((const float4*)xyz, (float4*)(out + OFF_XYZ), SZ_XYZ / 4);
    copy_f4_kernel<<<1024, 256>>>((const float4*)orf, (float4*)(out + OFF_ORF), SZ_ORF / 4);
    i2f_kernel<<<256, 256>>>(nidx, out + OFF_IDX, SZ_IDX);

    // 3) Main fused kernel
    lfa_kernel<<<NPTS, 256>>>(feature, orf, nidx, attn_W, out + OFF_OUT);
}

// round 3
// speedup vs baseline: 1.3236x; 1.3236x over previous
#include <cuda_runtime.h>
#include <cuda_bf16.h>
#include <math.h>
#include <stdint.h>

// Problem constants
#define Bq    2
#define Nq    8192
#define Kn    16
#define CINc  128
#define CRc   128
#define Dd    256
#define COUTc 256
#define EPSc  1e-5f
#define NEGc  0.2f

#define NPTS  (Bq * Nq)        // 16384 points
#define PPB   8                // points per block
#define NBLK  (NPTS / PPB)     // 2048 blocks

// Output layout (float32, concatenated)
#define OFF_XYZ   0
#define SZ_XYZ    (Bq * Nq * 3)
#define OFF_OUT   (OFF_XYZ + SZ_XYZ)
#define SZ_OUT    (Bq * Nq * COUTc)
#define OFF_ORF   (OFF_OUT + SZ_OUT)
#define SZ_ORF    (Bq * Nq * Kn * 10)
#define OFF_IDX   (OFF_ORF + SZ_ORF)
#define SZ_IDX    (Bq * Nq * Kn)

// Padded shared strides (bank-conflict avoidance)
#define PS_F  260              // feat_s row stride (floats)
#define PS_B  68               // Bs row stride (floats)

// Shared carve (floats)
#define SM_FEAT   0
#define SM_B      (SM_FEAT + 128 * PS_F)        // 33280
#define SM_POOL   (SM_B + 256 * PS_B)           // +17408 -> 50688
#define SM_FCEN   (SM_POOL + 256 * PPB)         // +2048  -> 52736  (pooled_t: [256][8])
#define SM_ORF    (SM_FCEN + 128 * PPB)         // +1024  -> 53760  (fcen_t: [128][8])
#define SM_IDX    (SM_ORF + PPB * 160)          // +1280  -> 55040
#define SM_TOTALF (SM_IDX + 128)                // +128   -> 55168 floats
#define SM_BYTES  (SM_TOTALF * 4)               // 220672 B

// BN-folded parameters (device globals; no allocation allowed)
__device__ float d_relWf[10 * CRc];
__device__ float d_relB[CRc];
__device__ float d_outWf[Dd * COUTc];
__device__ float d_outB[COUTc];
__device__ float d_scWf[CINc * COUTc];
__device__ float d_scB[COUTc];

// cvt to tf32 requires a .b32 destination register (ptxas rejects "=f")
__device__ __forceinline__ uint32_t to_tf32(float x) {
    uint32_t r;
    asm("cvt.rna.tf32.f32 %0, %1;" : "=r"(r) : "f"(x));
    return r;
}
__device__ __forceinline__ float to_tf32f(float x) {
    return __uint_as_float(to_tf32(x));
}

// ---------------------------------------------------------------------------
// Setup: fold BN into weights/biases + all passthrough copies in one kernel.
// ---------------------------------------------------------------------------
__global__ void fuse_and_copy_kernel(
    const float* __restrict__ rel_W, const float* __restrict__ rel_b,
    const float* __restrict__ rel_g, const float* __restrict__ rel_be,
    const float* __restrict__ rel_m, const float* __restrict__ rel_v,
    const float* __restrict__ out_W, const float* __restrict__ out_b,
    const float* __restrict__ out_g, const float* __restrict__ out_be,
    const float* __restrict__ out_m, const float* __restrict__ out_v,
    const float* __restrict__ sc_W,  const float* __restrict__ sc_b,
    const float* __restrict__ sc_g,  const float* __restrict__ sc_be,
    const float* __restrict__ sc_m,  const float* __restrict__ sc_v,
    const float* __restrict__ xyz,   const float* __restrict__ orf,
    const int*   __restrict__ nidx,  float* __restrict__ out)
{
    int t = blockIdx.x * blockDim.x + threadIdx.x;
    int stride = gridDim.x * blockDim.x;

    // Param folding
    for (int i = t; i < 10 * CRc; i += stride) {
        int c = i & (CRc - 1);
        d_relWf[i] = rel_W[i] * rel_g[c] * rsqrtf(rel_v[c] + EPSc);
    }
    for (int i = t; i < Dd * COUTc; i += stride) {
        int c = i & (COUTc - 1);
        d_outWf[i] = out_W[i] * out_g[c] * rsqrtf(out_v[c] + EPSc);
    }
    for (int i = t; i < CINc * COUTc; i += stride) {
        int c = i & (COUTc - 1);
        d_scWf[i] = sc_W[i] * sc_g[c] * rsqrtf(sc_v[c] + EPSc);
    }
    for (int i = t; i < CRc; i += stride) {
        float A = rel_g[i] * rsqrtf(rel_v[i] + EPSc);
        d_relB[i] = (rel_b[i] - rel_m[i]) * A + rel_be[i];
    }
    for (int i = t; i < COUTc; i += stride) {
        float A = out_g[i] * rsqrtf(out_v[i] + EPSc);
        d_outB[i] = (out_b[i] - out_m[i]) * A + out_be[i];
        float As = sc_g[i] * rsqrtf(sc_v[i] + EPSc);
        d_scB[i] = (sc_b[i] - sc_m[i]) * As + sc_be[i];
    }

    // Passthrough copies
    const float4* xs = (const float4*)xyz;
    float4* xd = (float4*)(out + OFF_XYZ);
    for (int i = t; i < SZ_XYZ / 4; i += stride) xd[i] = xs[i];
    const float4* os = (const float4*)orf;
    float4* od = (float4*)(out + OFF_ORF);
    for (int i = t; i < SZ_ORF / 4; i += stride) od[i] = os[i];
    float* id = out + OFF_IDX;
    for (int i = t; i < SZ_IDX; i += stride) id[i] = (float)nidx[i];
}

// ---------------------------------------------------------------------------
// Main kernel: 8 points / block, 256 threads (8 warps, warp w <-> point w).
//  Phase 1: gather + rel-MLP -> feat_s[128][256] (tf32-rounded)
//  Phase 2: logits via tf32 mma.sync m16n8k8, N-chunks of 64, full-K acc;
//           softmax over k + attention pooling inside the fragment (shfl).
//  Phase 3: main/shortcut GEMVs (FFMA) + leaky -> out.
// ---------------------------------------------------------------------------
__global__ __launch_bounds__(256, 1)
void lfa_mma_kernel(const float* __restrict__ feature,
                    const float* __restrict__ orf,
                    const int*   __restrict__ nidx,
                    const float* __restrict__ attn_W,
                    float*       __restrict__ out_feat)
{
    extern __shared__ float smem[];
    float* feat_s   = smem + SM_FEAT;   // [128][PS_F]
    float* Bs       = smem + SM_B;      // [256][PS_B]
    float* pooled_t = smem + SM_POOL;   // [256][8]  (channel-major, point minor)
    float* fcen_t   = smem + SM_FCEN;   // [128][8]
    float* orf_s    = smem + SM_ORF;    // [8][160]
    int*   idx_s    = (int*)(smem + SM_IDX);  // [128]

    const int tid = threadIdx.x;
    const int p0  = blockIdx.x * PPB;          // global point base
    const int b   = p0 >> 13;                  // batch

    // ---- Stage per-point small data ----
    if (tid < 128) idx_s[tid] = nidx[p0 * Kn + tid];
    for (int i = tid; i < PPB * 160; i += 256) orf_s[i] = orf[(size_t)p0 * 160 + i];
    for (int i = tid; i < PPB * CINc; i += 256) {
        int p = i & 7, c = i >> 3;             // transposed: fcen_t[c][p]
        fcen_t[c * PPB + p] = feature[(size_t)(p0 + p) * CINc + c];
    }
    __syncthreads();

    // ---- Gather neighbor features: 128 rows x 128 cols ----
    const float* fbase = feature + (size_t)b * Nq * CINc;
    for (int i = tid; i < 128 * 32; i += 256) {
        int r = i >> 5, c4 = i & 31;
        float4 v = *((const float4*)(fbase + (size_t)idx_s[r] * CINc) + c4);
        v.x = to_tf32f(v.x); v.y = to_tf32f(v.y);
        v.z = to_tf32f(v.z); v.w = to_tf32f(v.w);
        *(float4*)&feat_s[r * PS_F + c4 * 4] = v;
    }
    // ---- rel MLP (BN folded) -> feat_s[r][128+c] ----
    for (int i = tid; i < 128 * 128; i += 256) {
        int r = i >> 7, c = i & 127;
        float acc = d_relB[c];
        const float* o = &orf_s[(r >> 4) * 160 + (r & 15) * 10];
        #pragma unroll
        for (int d = 0; d < 10; d++) acc += o[d] * d_relWf[d * CRc + c];
        acc = (acc >= 0.f) ? acc : NEGc * acc;
        feat_s[r * PS_F + CINc + c] = to_tf32f(acc);
    }
    __syncthreads();

    const int w    = tid >> 5;          // warp == local point
    const int lane = tid & 31;
    const int g    = lane >> 2;         // 0..7
    const int t    = lane & 3;          // 0..3
    const int arow0 = (w * 16 + g) * PS_F;       // A rows g / g+8 of this point's tile
    const int arow8 = arow0 + 8 * PS_F;

    // ---- Logits GEMM in N-chunks of 64, full-K accumulate ----
    for (int nch = 0; nch < 4; nch++) {
        // Stage B chunk: Bs[k][n'] = attn_W[k][nch*64+n'], tf32-rounded
        for (int i = tid; i < 256 * 16; i += 256) {
            int k = i >> 4, n4 = i & 15;
            float4 v = *(const float4*)&attn_W[k * Dd + nch * 64 + n4 * 4];
            v.x = to_tf32f(v.x); v.y = to_tf32f(v.y);
            v.z = to_tf32f(v.z); v.w = to_tf32f(v.w);
            *(float4*)&Bs[k * PS_B + n4 * 4] = v;
        }
        __syncthreads();

        float acc[8][4];
        #pragma unroll
        for (int j = 0; j < 8; j++) {
            acc[j][0] = 0.f; acc[j][1] = 0.f; acc[j][2] = 0.f; acc[j][3] = 0.f;
        }

        #pragma unroll 4
        for (int s = 0; s < 32; s++) {
            const int ko = s * 8;
            uint32_t a0 = __float_as_uint(feat_s[arow0 + ko + t]);
            uint32_t a1 = __float_as_uint(feat_s[arow8 + ko + t]);
            uint32_t a2 = __float_as_uint(feat_s[arow0 + ko + t + 4]);
            uint32_t a3 = __float_as_uint(feat_s[arow8 + ko + t + 4]);
            #pragma unroll
            for (int j = 0; j < 8; j++) {
                uint32_t b0 = __float_as_uint(Bs[(ko + t) * PS_B + j * 8 + g]);
                uint32_t b1 = __float_as_uint(Bs[(ko + t + 4) * PS_B + j * 8 + g]);
                asm volatile(
                    "mma.sync.aligned.m16n8k8.row.col.f32.tf32.tf32.f32 "
                    "{%0,%1,%2,%3}, {%4,%5,%6,%7}, {%8,%9}, {%0,%1,%2,%3};"
                    : "+f"(acc[j][0]), "+f"(acc[j][1]), "+f"(acc[j][2]), "+f"(acc[j][3])
                    : "r"(a0), "r"(a1), "r"(a2), "r"(a3), "r"(b0), "r"(b1));
            }
        }

        // ---- Epilogue: softmax over k (16 rows of this m-tile) + pooling ----
        // Fragment: acc[j] = {(g,2t), (g,2t+1), (g+8,2t), (g+8,2t+1)} of 16x8 tile j.
        #pragma unroll
        for (int j = 0; j < 8; j++) {
            float c0 = acc[j][0], c1 = acc[j][1], c2 = acc[j][2], c3 = acc[j][3];
            float m0 = fmaxf(c0, c2), m1 = fmaxf(c1, c3);
            #pragma unroll
            for (int d = 4; d <= 16; d <<= 1) {
                m0 = fmaxf(m0, __shfl_xor_sync(0xffffffffu, m0, d));
                m1 = fmaxf(m1, __shfl_xor_sync(0xffffffffu, m1, d));
            }
            float e0 = __expf(c0 - m0), e1 = __expf(c1 - m1);
            float e2 = __expf(c2 - m0), e3 = __expf(c3 - m1);
            float s0 = e0 + e2, s1 = e1 + e3;
            #pragma unroll
            for (int d = 4; d <= 16; d <<= 1) {
                s0 += __shfl_xor_sync(0xffffffffu, s0, d);
                s1 += __shfl_xor_sync(0xffffffffu, s1, d);
            }
            const int C = nch * 64 + j * 8 + 2 * t;   // channel index
            float f0 = feat_s[arow0 + C];
            float f1 = feat_s[arow0 + C + 1];
            float f2 = feat_s[arow8 + C];
            float f3 = feat_s[arow8 + C + 1];
            float pp0 = e0 * f0 + e2 * f2;
            float pp1 = e1 * f1 + e3 * f3;
            #pragma unroll
            for (int d = 4; d <= 16; d <<= 1) {
                pp0 += __shfl_xor_sync(0xffffffffu, pp0, d);
                pp1 += __shfl_xor_sync(0xffffffffu, pp1, d);
            }
            if (g == 0) {
                pooled_t[C * PPB + w]       = pp0 / s0;   // transposed [channel][point]
                pooled_t[(C + 1) * PPB + w] = pp1 / s1;
            }
        }
        __syncthreads();   // Bs reuse + pooled visibility
    }

    // ---- Final: main = pooled @ outWf, sc = fcen @ scWf, leaky(main+sc) ----
    float mv[PPB], sv[PPB];
    #pragma unroll
    for (int p = 0; p < PPB; p++) { mv[p] = d_outB[tid]; sv[p] = d_scB[tid]; }

    #pragma unroll 2
    for (int d = 0; d < Dd; d++) {
        float wv = d_outWf[d * COUTc + tid];
        float4 pa = *(const float4*)&pooled_t[d * PPB];
        float4 pb = *(const float4*)&pooled_t[d * PPB + 4];
        mv[0] += pa.x * wv; mv[1] += pa.y * wv; mv[2] += pa.z * wv; mv[3] += pa.w * wv;
        mv[4] += pb.x * wv; mv[5] += pb.y * wv; mv[6] += pb.z * wv; mv[7] += pb.w * wv;
    }
    #pragma unroll 2
    for (int d = 0; d < CINc; d++) {
        float wv = d_scWf[d * COUTc + tid];
        float4 fa = *(const float4*)&fcen_t[d * PPB];
        float4 fb = *(const float4*)&fcen_t[d * PPB + 4];
        sv[0] += fa.x * wv; sv[1] += fa.y * wv; sv[2] += fa.z * wv; sv[3] += fa.w * wv;
        sv[4] += fb.x * wv; sv[5] += fb.y * wv; sv[6] += fb.z * wv; sv[7] += fb.w * wv;
    }
    #pragma unroll
    for (int p = 0; p < PPB; p++) {
        float o = mv[p] + sv[p];
        o = (o >= 0.f) ? o : NEGc * o;
        out_feat[(size_t)(p0 + p) * COUTc + tid] = o;
    }
}

// ---------------------------------------------------------------------------
extern "C" void kernel_launch(void* const* d_in, const int* in_sizes, int n_in,
                              void* d_out, int out_size)
{
    const float* xyz     = (const float*)d_in[0];
    const float* feature = (const float*)d_in[1];
    const float* orf     = (const float*)d_in[2];
    const int*   nidx    = (const int*)  d_in[3];
    const float* rel_W   = (const float*)d_in[4];
    const float* rel_b   = (const float*)d_in[5];
    const float* rel_g   = (const float*)d_in[6];
    const float* rel_be  = (const float*)d_in[7];
    const float* rel_m   = (const float*)d_in[8];
    const float* rel_v   = (const float*)d_in[9];
    const float* attn_W  = (const float*)d_in[10];
    const float* out_W   = (const float*)d_in[11];
    const float* out_b   = (const float*)d_in[12];
    const float* out_g   = (const float*)d_in[13];
    const float* out_be  = (const float*)d_in[14];
    const float* out_m   = (const float*)d_in[15];
    const float* out_v   = (const float*)d_in[16];
    const float* sc_W    = (const float*)d_in[17];
    const float* sc_b    = (const float*)d_in[18];
    const float* sc_g    = (const float*)d_in[19];
    const float* sc_be   = (const float*)d_in[20];
    const float* sc_m    = (const float*)d_in[21];
    const float* sc_v    = (const float*)d_in[22];

    float* out = (float*)d_out;

    cudaFuncSetAttribute(lfa_mma_kernel,
                         cudaFuncAttributeMaxDynamicSharedMemorySize, SM_BYTES);

    // 1) Fold BN params + passthrough copies (one kernel)
    fuse_and_copy_kernel<<<512, 256>>>(rel_W, rel_b, rel_g, rel_be, rel_m, rel_v,
                                       out_W, out_b, out_g, out_be, out_m, out_v,
                                       sc_W,  sc_b,  sc_g,  sc_be,  sc_m,  sc_v,
                                       xyz, orf, nidx, out);

    // 2) Main fused kernel (tf32 tensor-core logits)
    lfa_mma_kernel<<<NBLK, 256, SM_BYTES>>>(feature, orf, nidx, attn_W,
                                            out + OFF_OUT);
}

// round 4
// speedup vs baseline: 1.9711x; 1.4892x over previous
#include <cuda_runtime.h>
#include <cuda_bf16.h>
#include <math.h>
#include <stdint.h>

// Problem constants
#define Bq    2
#define Nq    8192
#define Kn    16
#define CINc  128
#define CRc   128
#define Dd    256
#define COUTc 256
#define EPSc  1e-5f
#define NEGc  0.2f

#define NPTS  (Bq * Nq)        // 16384 points
#define PPB   4                // points per block
#define NBLK  (NPTS / PPB)     // 4096 blocks
#define NTHR  128              // threads per block (4 warps; warp == local point)

// Output layout (float32, concatenated)
#define OFF_XYZ   0
#define SZ_XYZ    (Bq * Nq * 3)
#define OFF_OUT   (OFF_XYZ + SZ_XYZ)
#define SZ_OUT    (Bq * Nq * COUTc)
#define OFF_ORF   (OFF_OUT + SZ_OUT)
#define SZ_ORF    (Bq * Nq * Kn * 10)
#define OFF_IDX   (OFF_ORF + SZ_ORF)
#define SZ_IDX    (Bq * Nq * Kn)

// Padded shared stride for feat rows (bank-conflict-free A fragment loads)
#define PS_F  260

// Shared carve (floats): feat[64][260] | pooled_t[256][4] | fcen_t[128][4] | orf[4][160] | idx[64]
#define SM_FEAT   0
#define SM_POOL   (SM_FEAT + 64 * PS_F)        // 16640
#define SM_FCEN   (SM_POOL + 256 * PPB)        // 17664
#define SM_ORF    (SM_FCEN + 128 * PPB)        // 18176
#define SM_IDX    (SM_ORF + PPB * 160)         // 18816
#define SM_TOTALF (SM_IDX + 64)                // 18880 floats
#define SM_BYTES  (SM_TOTALF * 4)              // 75520 B  -> 3 blocks/SM

// BN-folded parameters + B fragment table (device globals; no allocation)
__device__ float d_relWf[10 * CRc];
__device__ float d_relB[CRc];
__device__ float d_outWf[Dd * COUTc];
__device__ float d_outB[COUTc];
__device__ float d_scWf[CINc * COUTc];
__device__ float d_scB[COUTc];
// attn_W pre-swizzled into m16n8k8 tf32 B-fragment layout:
// entry e = ((nch*32 + s)*4 + j2)*32 + lane ; float4 = {b0(j),b1(j),b0(j+1),b1(j+1)}
__device__ float4 d_attnFrag[4 * 32 * 4 * 32];   // 16384 float4 = 256 KB

// cvt to tf32 requires a .b32 destination register
__device__ __forceinline__ uint32_t to_tf32(float x) {
    uint32_t r;
    asm("cvt.rna.tf32.f32 %0, %1;" : "=r"(r) : "f"(x));
    return r;
}
__device__ __forceinline__ float to_tf32f(float x) {
    return __uint_as_float(to_tf32(x));
}

// ---------------------------------------------------------------------------
// Setup: fold BN into weights/biases, build B-fragment table, passthrough copies
// ---------------------------------------------------------------------------
__global__ void fuse_and_copy_kernel(
    const float* __restrict__ rel_W, const float* __restrict__ rel_b,
    const float* __restrict__ rel_g, const float* __restrict__ rel_be,
    const float* __restrict__ rel_m, const float* __restrict__ rel_v,
    const float* __restrict__ out_W, const float* __restrict__ out_b,
    const float* __restrict__ out_g, const float* __restrict__ out_be,
    const float* __restrict__ out_m, const float* __restrict__ out_v,
    const float* __restrict__ sc_W,  const float* __restrict__ sc_b,
    const float* __restrict__ sc_g,  const float* __restrict__ sc_be,
    const float* __restrict__ sc_m,  const float* __restrict__ sc_v,
    const float* __restrict__ attn_W,
    const float* __restrict__ xyz,   const float* __restrict__ orf,
    const int*   __restrict__ nidx,  float* __restrict__ out)
{
    int t = blockIdx.x * blockDim.x + threadIdx.x;
    int stride = gridDim.x * blockDim.x;

    // Param folding
    for (int i = t; i < 10 * CRc; i += stride) {
        int c = i & (CRc - 1);
        d_relWf[i] = rel_W[i] * rel_g[c] * rsqrtf(rel_v[c] + EPSc);
    }
    for (int i = t; i < Dd * COUTc; i += stride) {
        int c = i & (COUTc - 1);
        d_outWf[i] = out_W[i] * out_g[c] * rsqrtf(out_v[c] + EPSc);
    }
    for (int i = t; i < CINc * COUTc; i += stride) {
        int c = i & (COUTc - 1);
        d_scWf[i] = sc_W[i] * sc_g[c] * rsqrtf(sc_v[c] + EPSc);
    }
    for (int i = t; i < CRc; i += stride) {
        float A = rel_g[i] * rsqrtf(rel_v[i] + EPSc);
        d_relB[i] = (rel_b[i] - rel_m[i]) * A + rel_be[i];
    }
    for (int i = t; i < COUTc; i += stride) {
        float A = out_g[i] * rsqrtf(out_v[i] + EPSc);
        d_outB[i] = (out_b[i] - out_m[i]) * A + out_be[i];
        float As = sc_g[i] * rsqrtf(sc_v[i] + EPSc);
        d_scB[i] = (sc_b[i] - sc_m[i]) * As + sc_be[i];
    }

    // B fragment table (tf32-rounded)
    for (int e = t; e < 4 * 32 * 4 * 32; e += stride) {
        int lane = e & 31;
        int j2   = (e >> 5) & 3;
        int s    = (e >> 7) & 31;
        int nch  = (e >> 12) & 3;
        int g = lane >> 2, tt = lane & 3;
        int k0 = s * 8;
        int n0 = nch * 64 + (2 * j2)     * 8 + g;
        int n1 = nch * 64 + (2 * j2 + 1) * 8 + g;
        float4 v;
        v.x = to_tf32f(attn_W[(k0 + tt)     * Dd + n0]);
        v.y = to_tf32f(attn_W[(k0 + tt + 4) * Dd + n0]);
        v.z = to_tf32f(attn_W[(k0 + tt)     * Dd + n1]);
        v.w = to_tf32f(attn_W[(k0 + tt + 4) * Dd + n1]);
        d_attnFrag[e] = v;
    }

    // Passthrough copies
    const float4* xs = (const float4*)xyz;
    float4* xd = (float4*)(out + OFF_XYZ);
    for (int i = t; i < SZ_XYZ / 4; i += stride) xd[i] = xs[i];
    const float4* os = (const float4*)orf;
    float4* od = (float4*)(out + OFF_ORF);
    for (int i = t; i < SZ_ORF / 4; i += stride) od[i] = os[i];
    float* id = out + OFF_IDX;
    for (int i = t; i < SZ_IDX; i += stride) id[i] = (float)nidx[i];
}

// ---------------------------------------------------------------------------
// Main kernel: 4 points / block, 128 threads (4 warps; warp w <-> point w).
// ---------------------------------------------------------------------------
__global__ __launch_bounds__(NTHR, 2)
void lfa_mma_kernel(const float* __restrict__ feature,
                    const float* __restrict__ orf,
                    const int*   __restrict__ nidx,
                    float*       __restrict__ out_feat)
{
    extern __shared__ float smem[];
    float* feat_s   = smem + SM_FEAT;   // [64][PS_F]
    float* pooled_t = smem + SM_POOL;   // [256][4]  channel-major, point minor
    float* fcen_t   = smem + SM_FCEN;   // [128][4]
    float* orf_s    = smem + SM_ORF;    // [4][160]
    int*   idx_s    = (int*)(smem + SM_IDX);  // [64]

    const int tid = threadIdx.x;
    const int p0  = blockIdx.x * PPB;
    const int b   = p0 >> 13;

    // ---- Stage per-point small data ----
    if (tid < 64) idx_s[tid] = nidx[p0 * Kn + tid];
    for (int i = tid; i < PPB * 160; i += NTHR) orf_s[i] = orf[(size_t)p0 * 160 + i];
    for (int i = tid; i < PPB * CINc; i += NTHR) {
        int p = i & 3, c = i >> 2;
        fcen_t[c * PPB + p] = feature[(size_t)(p0 + p) * CINc + c];
    }
    __syncthreads();

    // ---- Gather neighbor features: 64 rows x 128 cols ----
    const float* fbase = feature + (size_t)b * Nq * CINc;
    for (int i = tid; i < 64 * 32; i += NTHR) {
        int r = i >> 5, c4 = i & 31;
        float4 v = *((const float4*)(fbase + (size_t)idx_s[r] * CINc) + c4);
        v.x = to_tf32f(v.x); v.y = to_tf32f(v.y);
        v.z = to_tf32f(v.z); v.w = to_tf32f(v.w);
        *(float4*)&feat_s[r * PS_F + c4 * 4] = v;
    }
    // ---- rel MLP (BN folded) -> feat_s[r][128+c] ----
    for (int i = tid; i < 64 * 128; i += NTHR) {
        int r = i >> 7, c = i & 127;
        float acc = d_relB[c];
        const float* o = &orf_s[(r >> 4) * 160 + (r & 15) * 10];
        #pragma unroll
        for (int d = 0; d < 10; d++) acc += o[d] * d_relWf[d * CRc + c];
        acc = (acc >= 0.f) ? acc : NEGc * acc;
        feat_s[r * PS_F + CINc + c] = to_tf32f(acc);
    }
    __syncthreads();

    const int w    = tid >> 5;          // warp == local point (0..3)
    const int lane = tid & 31;
    const int g    = lane >> 2;
    const int t    = lane & 3;
    const int arow0 = (w * 16 + g) * PS_F;
    const int arow8 = arow0 + 8 * PS_F;

    // ---- Logits GEMM (barrier-free across nch), softmax+pool in fragment ----
    #pragma unroll 1
    for (int nch = 0; nch < 4; nch++) {
        float acc[8][4];
        #pragma unroll
        for (int j = 0; j < 8; j++) {
            acc[j][0] = 0.f; acc[j][1] = 0.f; acc[j][2] = 0.f; acc[j][3] = 0.f;
        }

        const float4* bfrag = d_attnFrag + (size_t)(nch * 32) * 4 * 32 + lane;

        #pragma unroll 4
        for (int s = 0; s < 32; s++) {
            const int ko = s * 8;
            uint32_t a0 = __float_as_uint(feat_s[arow0 + ko + t]);
            uint32_t a1 = __float_as_uint(feat_s[arow8 + ko + t]);
            uint32_t a2 = __float_as_uint(feat_s[arow0 + ko + t + 4]);
            uint32_t a3 = __float_as_uint(feat_s[arow8 + ko + t + 4]);
            const float4* bs = bfrag + (size_t)s * 4 * 32;
            #pragma unroll
            for (int j2 = 0; j2 < 4; j2++) {
                float4 bv = bs[j2 * 32];
                asm volatile(
                    "mma.sync.aligned.m16n8k8.row.col.f32.tf32.tf32.f32 "
                    "{%0,%1,%2,%3}, {%4,%5,%6,%7}, {%8,%9}, {%0,%1,%2,%3};"
                    : "+f"(acc[2*j2][0]), "+f"(acc[2*j2][1]),
                      "+f"(acc[2*j2][2]), "+f"(acc[2*j2][3])
                    : "r"(a0), "r"(a1), "r"(a2), "r"(a3),
                      "r"(__float_as_uint(bv.x)), "r"(__float_as_uint(bv.y)));
                asm volatile(
                    "mma.sync.aligned.m16n8k8.row.col.f32.tf32.tf32.f32 "
                    "{%0,%1,%2,%3}, {%4,%5,%6,%7}, {%8,%9}, {%0,%1,%2,%3};"
                    : "+f"(acc[2*j2+1][0]), "+f"(acc[2*j2+1][1]),
                      "+f"(acc[2*j2+1][2]), "+f"(acc[2*j2+1][3])
                    : "r"(a0), "r"(a1), "r"(a2), "r"(a3),
                      "r"(__float_as_uint(bv.z)), "r"(__float_as_uint(bv.w)));
            }
        }

        // Softmax over k (16 rows) + attention pooling, per 16x8 tile j
        #pragma unroll
        for (int j = 0; j < 8; j++) {
            float c0 = acc[j][0], c1 = acc[j][1], c2 = acc[j][2], c3 = acc[j][3];
            float m0 = fmaxf(c0, c2), m1 = fmaxf(c1, c3);
            #pragma unroll
            for (int d = 4; d <= 16; d <<= 1) {
                m0 = fmaxf(m0, __shfl_xor_sync(0xffffffffu, m0, d));
                m1 = fmaxf(m1, __shfl_xor_sync(0xffffffffu, m1, d));
            }
            float e0 = __expf(c0 - m0), e1 = __expf(c1 - m1);
            float e2 = __expf(c2 - m0), e3 = __expf(c3 - m1);
            float s0 = e0 + e2, s1 = e1 + e3;
            #pragma unroll
            for (int d = 4; d <= 16; d <<= 1) {
                s0 += __shfl_xor_sync(0xffffffffu, s0, d);
                s1 += __shfl_xor_sync(0xffffffffu, s1, d);
            }
            const int C = nch * 64 + j * 8 + 2 * t;
            float f0 = feat_s[arow0 + C];
            float f1 = feat_s[arow0 + C + 1];
            float f2 = feat_s[arow8 + C];
            float f3 = feat_s[arow8 + C + 1];
            float pp0 = e0 * f0 + e2 * f2;
            float pp1 = e1 * f1 + e3 * f3;
            #pragma unroll
            for (int d = 4; d <= 16; d <<= 1) {
                pp0 += __shfl_xor_sync(0xffffffffu, pp0, d);
                pp1 += __shfl_xor_sync(0xffffffffu, pp1, d);
            }
            if (g == 0) {
                pooled_t[C * PPB + w]       = pp0 / s0;
                pooled_t[(C + 1) * PPB + w] = pp1 / s1;
            }
        }
    }
    __syncthreads();   // pooled_t visible to all warps

    // ---- Final GEMVs: each thread handles channels tid and tid+128 ----
    float mv0[PPB], mv1[PPB], sv0[PPB], sv1[PPB];
    #pragma unroll
    for (int p = 0; p < PPB; p++) {
        mv0[p] = d_outB[tid];       mv1[p] = d_outB[tid + 128];
        sv0[p] = d_scB[tid];        sv1[p] = d_scB[tid + 128];
    }

    #pragma unroll 2
    for (int d = 0; d < Dd; d++) {
        float w0 = d_outWf[d * COUTc + tid];
        float w1 = d_outWf[d * COUTc + tid + 128];
        float4 pa = *(const float4*)&pooled_t[d * PPB];
        mv0[0] += pa.x * w0; mv0[1] += pa.y * w0; mv0[2] += pa.z * w0; mv0[3] += pa.w * w0;
        mv1[0] += pa.x * w1; mv1[1] += pa.y * w1; mv1[2] += pa.z * w1; mv1[3] += pa.w * w1;
    }
    #pragma unroll 2
    for (int d = 0; d < CINc; d++) {
        float w0 = d_scWf[d * COUTc + tid];
        float w1 = d_scWf[d * COUTc + tid + 128];
        float4 fa = *(const float4*)&fcen_t[d * PPB];
        sv0[0] += fa.x * w0; sv0[1] += fa.y * w0; sv0[2] += fa.z * w0; sv0[3] += fa.w * w0;
        sv1[0] += fa.x * w1; sv1[1] += fa.y * w1; sv1[2] += fa.z * w1; sv1[3] += fa.w * w1;
    }
    #pragma unroll
    for (int p = 0; p < PPB; p++) {
        float o0 = mv0[p] + sv0[p];
        o0 = (o0 >= 0.f) ? o0 : NEGc * o0;
        float o1 = mv1[p] + sv1[p];
        o1 = (o1 >= 0.f) ? o1 : NEGc * o1;
        out_feat[(size_t)(p0 + p) * COUTc + tid]       = o0;
        out_feat[(size_t)(p0 + p) * COUTc + tid + 128] = o1;
    }
}

// ---------------------------------------------------------------------------
extern "C" void kernel_launch(void* const* d_in, const int* in_sizes, int n_in,
                              void* d_out, int out_size)
{
    const float* xyz     = (const float*)d_in[0];
    const float* feature = (const float*)d_in[1];
    const float* orf     = (const float*)d_in[2];
    const int*   nidx    = (const int*)  d_in[3];
    const float* rel_W   = (const float*)d_in[4];
    const float* rel_b   = (const float*)d_in[5];
    const float* rel_g   = (const float*)d_in[6];
    const float* rel_be  = (const float*)d_in[7];
    const float* rel_m   = (const float*)d_in[8];
    const float* rel_v   = (const float*)d_in[9];
    const float* attn_W  = (const float*)d_in[10];
    const float* out_W   = (const float*)d_in[11];
    const float* out_b   = (const float*)d_in[12];
    const float* out_g   = (const float*)d_in[13];
    const float* out_be  = (const float*)d_in[14];
    const float* out_m   = (const float*)d_in[15];
    const float* out_v   = (const float*)d_in[16];
    const float* sc_W    = (const float*)d_in[17];
    const float* sc_b    = (const float*)d_in[18];
    const float* sc_g    = (const float*)d_in[19];
    const float* sc_be   = (const float*)d_in[20];
    const float* sc_m    = (const float*)d_in[21];
    const float* sc_v    = (const float*)d_in[22];

    float* out = (float*)d_out;

    cudaFuncSetAttribute(lfa_mma_kernel,
                         cudaFuncAttributeMaxDynamicSharedMemorySize, SM_BYTES);

    fuse_and_copy_kernel<<<512, 256>>>(rel_W, rel_b, rel_g, rel_be, rel_m, rel_v,
                                       out_W, out_b, out_g, out_be, out_m, out_v,
                                       sc_W,  sc_b,  sc_g,  sc_be,  sc_m,  sc_v,
                                       attn_W, xyz, orf, nidx, out);

    lfa_mma_kernel<<<NBLK, NTHR, SM_BYTES>>>(feature, orf, nidx, out + OFF_OUT);
}

// round 5
// speedup vs baseline: 5.3266x; 2.7023x over previous
#include <cuda_runtime.h>
#include <cuda_bf16.h>
#include <math.h>
#include <stdint.h>

// Problem constants
#define Bq    2
#define Nq    8192
#define Kn    16
#define CINc  128
#define CRc   128
#define Dd    256
#define COUTc 256
#define EPSc  1e-5f
#define NEGc  0.2f

#define NPTS  (Bq * Nq)        // 16384 points
#define PPB   4                // points per block (attn kernel)
#define NBLK  (NPTS / PPB)     // 4096 blocks
#define NTHR  128

// Output layout (float32, concatenated)
#define OFF_XYZ   0
#define SZ_XYZ    (Bq * Nq * 3)
#define OFF_OUT   (OFF_XYZ + SZ_XYZ)
#define SZ_OUT    (Bq * Nq * COUTc)
#define OFF_ORF   (OFF_OUT + SZ_OUT)
#define SZ_ORF    (Bq * Nq * Kn * 10)
#define OFF_IDX   (OFF_ORF + SZ_ORF)
#define SZ_IDX    (Bq * Nq * Kn)

// ---- attn kernel shared layout (32-bit words) ----
#define PS_FB   132            // feat_b row stride in uint32 (128 pairs + 4 pad)
#define SMA_FEAT 0
#define SMA_ORF  (SMA_FEAT + 64 * PS_FB)    // 8448
#define SMA_RELW (SMA_ORF + PPB * 160)      // 9088
#define SMA_RELB (SMA_RELW + 10 * CRc)      // 10368
#define SMA_IDX  (SMA_RELB + CRc)           // 10496
#define SMA_TOT  (SMA_IDX + 64)             // 10560 words = 42240 B (static smem)

// ---- gemm kernel ----
#define GM_TILE  32            // points per gemm block
#define GK       (Dd + CINc)   // 384
#define PS_A     388           // As row stride (floats): 384 + 4 pad
#define GSM_BYTES (GM_TILE * PS_A * 4)   // 49664 B (dynamic smem)

// Device globals (no allocation allowed)
__device__ float d_relWf[10 * CRc];
__device__ float d_relB[CRc];
__device__ float d_biasC[COUTc];
// attn_W in bf16 m16n8k16 B-fragment layout:
// e = ((nch*16 + s)*4 + j2)*32 + lane ; uint4 = {b0(j),b1(j),b0(j+1),b1(j+1)}
__device__ uint4 d_attnFrag[4 * 16 * 4 * 32];        // 8192 * 16B = 128 KB
// [outWf ; scWf] (BN-folded) in tf32 m16n8k8 B-fragment layout:
// e = (s*16 + j2)*32 + lane ; s: 48 k8-steps, j2: 16 n16-pairs
__device__ uint4 d_wFrag[48 * 16 * 32];              // 24576 * 16B = 384 KB
// pooled scratch [NPTS][256]
__device__ float d_pooled[(size_t)NPTS * Dd];        // 16.8 MB

__device__ __forceinline__ uint32_t to_tf32(float x) {
    uint32_t r;
    asm("cvt.rna.tf32.f32 %0, %1;" : "=r"(r) : "f"(x));
    return r;
}
__device__ __forceinline__ float to_tf32f(float x) {
    return __uint_as_float(to_tf32(x));
}
__device__ __forceinline__ uint32_t pack_bf2(float lo, float hi) {
    __nv_bfloat162 h = __floats2bfloat162_rn(lo, hi);
    return *reinterpret_cast<uint32_t*>(&h);
}

// folded weight for the combined [outW;scW] GEMM
__device__ __forceinline__ float wc_fold(int k, int n,
    const float* out_W, const float* out_g, const float* out_v,
    const float* sc_W,  const float* sc_g,  const float* sc_v)
{
    if (k < Dd)  return out_W[k * COUTc + n] * out_g[n] * rsqrtf(out_v[n] + EPSc);
    return sc_W[(k - Dd) * COUTc + n] * sc_g[n] * rsqrtf(sc_v[n] + EPSc);
}

// ---------------------------------------------------------------------------
// Setup: fold BN, build fragment tables, passthrough copies.
// ---------------------------------------------------------------------------
__global__ void fuse_and_copy_kernel(
    const float* __restrict__ rel_W, const float* __restrict__ rel_b,
    const float* __restrict__ rel_g, const float* __restrict__ rel_be,
    const float* __restrict__ rel_m, const float* __restrict__ rel_v,
    const float* __restrict__ out_W, const float* __restrict__ out_b,
    const float* __restrict__ out_g, const float* __restrict__ out_be,
    const float* __restrict__ out_m, const float* __restrict__ out_v,
    const float* __restrict__ sc_W,  const float* __restrict__ sc_b,
    const float* __restrict__ sc_g,  const float* __restrict__ sc_be,
    const float* __restrict__ sc_m,  const float* __restrict__ sc_v,
    const float* __restrict__ attn_W,
    const float* __restrict__ xyz,   const float* __restrict__ orf,
    const int*   __restrict__ nidx,  float* __restrict__ out)
{
    int t0 = blockIdx.x * blockDim.x + threadIdx.x;
    int stride = gridDim.x * blockDim.x;

    for (int i = t0; i < 10 * CRc; i += stride) {
        int c = i & (CRc - 1);
        d_relWf[i] = rel_W[i] * rel_g[c] * rsqrtf(rel_v[c] + EPSc);
    }
    for (int i = t0; i < CRc; i += stride) {
        float A = rel_g[i] * rsqrtf(rel_v[i] + EPSc);
        d_relB[i] = (rel_b[i] - rel_m[i]) * A + rel_be[i];
    }
    for (int i = t0; i < COUTc; i += stride) {
        float Ao = out_g[i] * rsqrtf(out_v[i] + EPSc);
        float As = sc_g[i] * rsqrtf(sc_v[i] + EPSc);
        d_biasC[i] = (out_b[i] - out_m[i]) * Ao + out_be[i]
                   + (sc_b[i] - sc_m[i]) * As + sc_be[i];
    }

    // attn bf16 fragment table
    for (int e = t0; e < 4 * 16 * 4 * 32; e += stride) {
        int lane = e & 31, j2 = (e >> 5) & 3, s = (e >> 7) & 15, nch = e >> 11;
        int g = lane >> 2, tt = lane & 3, k0 = s * 16;
        int n0 = nch * 64 + (2 * j2) * 8 + g;
        int n1 = n0 + 8;
        uint4 v;
        v.x = pack_bf2(attn_W[(k0 + 2*tt)     * Dd + n0], attn_W[(k0 + 2*tt + 1) * Dd + n0]);
        v.y = pack_bf2(attn_W[(k0 + 2*tt + 8) * Dd + n0], attn_W[(k0 + 2*tt + 9) * Dd + n0]);
        v.z = pack_bf2(attn_W[(k0 + 2*tt)     * Dd + n1], attn_W[(k0 + 2*tt + 1) * Dd + n1]);
        v.w = pack_bf2(attn_W[(k0 + 2*tt + 8) * Dd + n1], attn_W[(k0 + 2*tt + 9) * Dd + n1]);
        d_attnFrag[e] = v;
    }

    // combined [outW;scW] tf32 fragment table
    for (int e = t0; e < 48 * 16 * 32; e += stride) {
        int lane = e & 31, j2 = (e >> 5) & 15, s = e >> 9;   // s 0..47
        int g = lane >> 2, tt = lane & 3, k0 = s * 8;
        int n0 = (2 * j2) * 8 + g;
        int n1 = n0 + 8;
        uint4 v;
        v.x = to_tf32(wc_fold(k0 + tt,     n0, out_W, out_g, out_v, sc_W, sc_g, sc_v));
        v.y = to_tf32(wc_fold(k0 + tt + 4, n0, out_W, out_g, out_v, sc_W, sc_g, sc_v));
        v.z = to_tf32(wc_fold(k0 + tt,     n1, out_W, out_g, out_v, sc_W, sc_g, sc_v));
        v.w = to_tf32(wc_fold(k0 + tt + 4, n1, out_W, out_g, out_v, sc_W, sc_g, sc_v));
        d_wFrag[e] = v;
    }

    // Passthrough copies
    const float4* xs = (const float4*)xyz;
    float4* xd = (float4*)(out + OFF_XYZ);
    for (int i = t0; i < SZ_XYZ / 4; i += stride) xd[i] = xs[i];
    const float4* os = (const float4*)orf;
    float4* od = (float4*)(out + OFF_ORF);
    for (int i = t0; i < SZ_ORF / 4; i += stride) od[i] = os[i];
    float* id = out + OFF_IDX;
    for (int i = t0; i < SZ_IDX; i += stride) id[i] = (float)nidx[i];
}

// ---------------------------------------------------------------------------
// Attention kernel: 4 points/block, 128 threads (warp w == point w), bf16 MMA.
// Writes pooled[point][256] to global scratch.
// ---------------------------------------------------------------------------
__global__ __launch_bounds__(NTHR, 4)
void lfa_attn_kernel(const float* __restrict__ feature,
                     const float* __restrict__ orf,
                     const int*   __restrict__ nidx)
{
    __shared__ uint32_t smem[SMA_TOT];
    uint32_t* feat_b = smem + SMA_FEAT;           // [64][PS_FB] bf16x2
    float* orf_s  = (float*)(smem + SMA_ORF);     // [4][160]
    float* relW_s = (float*)(smem + SMA_RELW);    // [10][128]
    float* relB_s = (float*)(smem + SMA_RELB);    // [128]
    int*   idx_s  = (int*)(smem + SMA_IDX);       // [64]

    const int tid = threadIdx.x;
    const int p0  = blockIdx.x * PPB;
    const int b   = p0 >> 13;

    // ---- Stage small data + rel weights ----
    if (tid < 64) idx_s[tid] = nidx[p0 * Kn + tid];
    for (int i = tid; i < PPB * 160; i += NTHR) orf_s[i] = orf[(size_t)p0 * 160 + i];
    for (int i = tid; i < 10 * CRc; i += NTHR) relW_s[i] = d_relWf[i];
    if (tid < CRc) relB_s[tid] = d_relB[tid];
    __syncthreads();

    // ---- Gather neighbor features -> bf16 pairs ----
    const float* fbase = feature + (size_t)b * Nq * CINc;
    for (int i = tid; i < 64 * 32; i += NTHR) {
        int r = i >> 5, c4 = i & 31;
        float4 v = *((const float4*)(fbase + (size_t)idx_s[r] * CINc) + c4);
        uint2 pk;
        pk.x = pack_bf2(v.x, v.y);
        pk.y = pack_bf2(v.z, v.w);
        *(uint2*)&feat_b[r * PS_FB + c4 * 2] = pk;
    }
    // ---- rel MLP (BN folded) -> bf16 pairs at cols 128..255 ----
    for (int i = tid; i < 64 * 64; i += NTHR) {
        int r = i >> 6, c2 = i & 63;
        float a0 = relB_s[2 * c2], a1 = relB_s[2 * c2 + 1];
        const float* o = &orf_s[(r >> 4) * 160 + (r & 15) * 10];
        #pragma unroll
        for (int d = 0; d < 10; d++) {
            float od = o[d];
            a0 += od * relW_s[d * CRc + 2 * c2];
            a1 += od * relW_s[d * CRc + 2 * c2 + 1];
        }
        a0 = (a0 >= 0.f) ? a0 : NEGc * a0;
        a1 = (a1 >= 0.f) ? a1 : NEGc * a1;
        feat_b[r * PS_FB + 64 + c2] = pack_bf2(a0, a1);
    }
    __syncthreads();

    const int w    = tid >> 5;
    const int lane = tid & 31;
    const int g    = lane >> 2;
    const int t    = lane & 3;
    const int arow0 = (w * 16 + g) * PS_FB;
    const int arow8 = arow0 + 8 * PS_FB;
    float* poolrow = d_pooled + (size_t)(p0 + w) * Dd;

    // ---- Logits (bf16 m16n8k16) + softmax + pooling, barrier-free ----
    #pragma unroll 1
    for (int nch = 0; nch < 4; nch++) {
        float acc[8][4];
        #pragma unroll
        for (int j = 0; j < 8; j++) {
            acc[j][0] = 0.f; acc[j][1] = 0.f; acc[j][2] = 0.f; acc[j][3] = 0.f;
        }

        const uint4* bfrag = d_attnFrag + (size_t)(nch * 16) * 128 + lane;

        #pragma unroll 4
        for (int s = 0; s < 16; s++) {
            const int pc = s * 8;     // packed-pair col base (k0 = 16s)
            uint32_t a0 = feat_b[arow0 + pc + t];
            uint32_t a1 = feat_b[arow8 + pc + t];
            uint32_t a2 = feat_b[arow0 + pc + t + 4];
            uint32_t a3 = feat_b[arow8 + pc + t + 4];
            const uint4* bs = bfrag + s * 128;
            #pragma unroll
            for (int j2 = 0; j2 < 4; j2++) {
                uint4 bv = bs[j2 * 32];
                asm volatile(
                    "mma.sync.aligned.m16n8k16.row.col.f32.bf16.bf16.f32 "
                    "{%0,%1,%2,%3}, {%4,%5,%6,%7}, {%8,%9}, {%0,%1,%2,%3};"
                    : "+f"(acc[2*j2][0]), "+f"(acc[2*j2][1]),
                      "+f"(acc[2*j2][2]), "+f"(acc[2*j2][3])
                    : "r"(a0), "r"(a1), "r"(a2), "r"(a3), "r"(bv.x), "r"(bv.y));
                asm volatile(
                    "mma.sync.aligned.m16n8k16.row.col.f32.bf16.bf16.f32 "
                    "{%0,%1,%2,%3}, {%4,%5,%6,%7}, {%8,%9}, {%0,%1,%2,%3};"
                    : "+f"(acc[2*j2+1][0]), "+f"(acc[2*j2+1][1]),
                      "+f"(acc[2*j2+1][2]), "+f"(acc[2*j2+1][3])
                    : "r"(a0), "r"(a1), "r"(a2), "r"(a3), "r"(bv.z), "r"(bv.w));
            }
        }

        // Softmax over k (no max-subtract: |logit| << 88) + pooling
        #pragma unroll
        for (int j = 0; j < 8; j++) {
            float e0 = __expf(acc[j][0]);
            float e1 = __expf(acc[j][1]);
            float e2 = __expf(acc[j][2]);
            float e3 = __expf(acc[j][3]);
            float s0 = e0 + e2, s1 = e1 + e3;

            // feat values at (rows g,g+8; cols C,C+1), C = nch*64 + j*8 + 2t
            uint32_t u01 = feat_b[arow0 + nch * 32 + j * 4 + t];
            uint32_t u23 = feat_b[arow8 + nch * 32 + j * 4 + t];
            float2 f01 = __bfloat1622float2(*reinterpret_cast<__nv_bfloat162*>(&u01));
            float2 f23 = __bfloat1622float2(*reinterpret_cast<__nv_bfloat162*>(&u23));
            float pp0 = e0 * f01.x + e2 * f23.x;
            float pp1 = e1 * f01.y + e3 * f23.y;

            #pragma unroll
            for (int d = 4; d <= 16; d <<= 1) {
                s0  += __shfl_xor_sync(0xffffffffu, s0, d);
                s1  += __shfl_xor_sync(0xffffffffu, s1, d);
                pp0 += __shfl_xor_sync(0xffffffffu, pp0, d);
                pp1 += __shfl_xor_sync(0xffffffffu, pp1, d);
            }
            if (g == 0) {
                const int C = nch * 64 + j * 8 + 2 * t;
                poolrow[C]     = pp0 / s0;
                poolrow[C + 1] = pp1 / s1;
            }
        }
    }
}

// ---------------------------------------------------------------------------
// Final GEMM: out = leaky([pooled | feature] @ [outWf;scWf] + bias)
// M=16384, N=256, K=384, tf32 MMA. Block: 32 points, 256 threads (8 warps).
// warp = (r, cs): r=row-tile(2 x m16), cs=col-seg(4 x n64)
// ---------------------------------------------------------------------------
__global__ __launch_bounds__(256, 2)
void lfa_gemm_kernel(const float* __restrict__ feature,
                     float*       __restrict__ out_feat)
{
    extern __shared__ float As[];      // [32][PS_A]

    const int tid = threadIdx.x;
    const int m0b = blockIdx.x * GM_TILE;

    // ---- Stage A tile: cols 0..255 = pooled, 256..383 = feature ----
    for (int i = tid; i < GM_TILE * 96; i += 256) {
        int row = i / 96, q = i % 96;
        int m = m0b + row;
        float4 v;
        if (q < 64) v = *((const float4*)(d_pooled + (size_t)m * Dd) + q);
        else        v = *((const float4*)(feature + (size_t)m * CINc) + (q - 64));
        v.x = to_tf32f(v.x); v.y = to_tf32f(v.y);
        v.z = to_tf32f(v.z); v.w = to_tf32f(v.w);
        *(float4*)&As[row * PS_A + q * 4] = v;
    }
    __syncthreads();

    const int w    = tid >> 5;
    const int lane = tid & 31;
    const int r    = w >> 2;            // 0..1
    const int cs   = w & 3;             // 0..3
    const int g    = lane >> 2;
    const int t    = lane & 3;
    const int arow0 = (r * 16 + g) * PS_A;
    const int arow8 = arow0 + 8 * PS_A;

    float acc[8][4];
    #pragma unroll
    for (int j = 0; j < 8; j++) {
        acc[j][0] = 0.f; acc[j][1] = 0.f; acc[j][2] = 0.f; acc[j][3] = 0.f;
    }

    const uint4* bfrag = d_wFrag + (size_t)(cs * 4) * 32 + lane;

    #pragma unroll 4
    for (int s = 0; s < 48; s++) {
        const int k0 = s * 8;
        uint32_t a0 = __float_as_uint(As[arow0 + k0 + t]);
        uint32_t a1 = __float_as_uint(As[arow8 + k0 + t]);
        uint32_t a2 = __float_as_uint(As[arow0 + k0 + t + 4]);
        uint32_t a3 = __float_as_uint(As[arow8 + k0 + t + 4]);
        const uint4* bs = bfrag + (size_t)s * 16 * 32;
        #pragma unroll
        for (int j2 = 0; j2 < 4; j2++) {
            uint4 bv = bs[j2 * 32];
            asm volatile(
                "mma.sync.aligned.m16n8k8.row.col.f32.tf32.tf32.f32 "
                "{%0,%1,%2,%3}, {%4,%5,%6,%7}, {%8,%9}, {%0,%1,%2,%3};"
                : "+f"(acc[2*j2][0]), "+f"(acc[2*j2][1]),
                  "+f"(acc[2*j2][2]), "+f"(acc[2*j2][3])
                : "r"(a0), "r"(a1), "r"(a2), "r"(a3), "r"(bv.x), "r"(bv.y));
            asm volatile(
                "mma.sync.aligned.m16n8k8.row.col.f32.tf32.tf32.f32 "
                "{%0,%1,%2,%3}, {%4,%5,%6,%7}, {%8,%9}, {%0,%1,%2,%3};"
                : "+f"(acc[2*j2+1][0]), "+f"(acc[2*j2+1][1]),
                  "+f"(acc[2*j2+1][2]), "+f"(acc[2*j2+1][3])
                : "r"(a0), "r"(a1), "r"(a2), "r"(a3), "r"(bv.z), "r"(bv.w));
        }
    }

    // ---- Epilogue: bias + leaky + store ----
    const int mrow0 = m0b + r * 16 + g;
    #pragma unroll
    for (int j = 0; j < 8; j++) {
        const int n0 = cs * 64 + j * 8 + 2 * t;
        float2 bias = *(const float2*)&d_biasC[n0];
        float o0 = acc[j][0] + bias.x;
        float o1 = acc[j][1] + bias.y;
        float o2 = acc[j][2] + bias.x;
        float o3 = acc[j][3] + bias.y;
        o0 = (o0 >= 0.f) ? o0 : NEGc * o0;
        o1 = (o1 >= 0.f) ? o1 : NEGc * o1;
        o2 = (o2 >= 0.f) ? o2 : NEGc * o2;
        o3 = (o3 >= 0.f) ? o3 : NEGc * o3;
        *(float2*)&out_feat[(size_t)mrow0 * COUTc + n0]       = make_float2(o0, o1);
        *(float2*)&out_feat[(size_t)(mrow0 + 8) * COUTc + n0] = make_float2(o2, o3);
    }
}

// ---------------------------------------------------------------------------
extern "C" void kernel_launch(void* const* d_in, const int* in_sizes, int n_in,
                              void* d_out, int out_size)
{
    const float* xyz     = (const float*)d_in[0];
    const float* feature = (const float*)d_in[1];
    const float* orf     = (const float*)d_in[2];
    const int*   nidx    = (const int*)  d_in[3];
    const float* rel_W   = (const float*)d_in[4];
    const float* rel_b   = (const float*)d_in[5];
    const float* rel_g   = (const float*)d_in[6];
    const float* rel_be  = (const float*)d_in[7];
    const float* rel_m   = (const float*)d_in[8];
    const float* rel_v   = (const float*)d_in[9];
    const float* attn_W  = (const float*)d_in[10];
    const float* out_W   = (const float*)d_in[11];
    const float* out_b   = (const float*)d_in[12];
    const float* out_g   = (const float*)d_in[13];
    const float* out_be  = (const float*)d_in[14];
    const float* out_m   = (const float*)d_in[15];
    const float* out_v   = (const float*)d_in[16];
    const float* sc_W    = (const float*)d_in[17];
    const float* sc_b    = (const float*)d_in[18];
    const float* sc_g    = (const float*)d_in[19];
    const float* sc_be   = (const float*)d_in[20];
    const float* sc_m    = (const float*)d_in[21];
    const float* sc_v    = (const float*)d_in[22];

    float* out = (float*)d_out;

    cudaFuncSetAttribute(lfa_gemm_kernel,
                         cudaFuncAttributeMaxDynamicSharedMemorySize, GSM_BYTES);

    fuse_and_copy_kernel<<<512, 256>>>(rel_W, rel_b, rel_g, rel_be, rel_m, rel_v,
                                       out_W, out_b, out_g, out_be, out_m, out_v,
                                       sc_W,  sc_b,  sc_g,  sc_be,  sc_m,  sc_v,
                                       attn_W, xyz, orf, nidx, out);

    lfa_attn_kernel<<<NBLK, NTHR>>>(feature, orf, nidx);

    lfa_gemm_kernel<<<NPTS / GM_TILE, 256, GSM_BYTES>>>(feature, out + OFF_OUT);
}

// round 6
// speedup vs baseline: 5.6725x; 1.0649x over previous
#include <cuda_runtime.h>
#include <cuda_bf16.h>
#include <math.h>
#include <stdint.h>

// Problem constants
#define Bq    2
#define Nq    8192
#define Kn    16
#define CINc  128
#define CRc   128
#define Dd    256
#define COUTc 256
#define EPSc  1e-5f
#define NEGc  0.2f

#define NPTS  (Bq * Nq)        // 16384 points
#define PPB   4                // points per block (attn kernel)
#define NBLK  (NPTS / PPB)     // 4096 blocks
#define NTHR  128

// Output layout (float32, concatenated)
#define OFF_XYZ   0
#define SZ_XYZ    (Bq * Nq * 3)
#define OFF_OUT   (OFF_XYZ + SZ_XYZ)
#define SZ_OUT    (Bq * Nq * COUTc)
#define OFF_ORF   (OFF_OUT + SZ_OUT)
#define SZ_ORF    (Bq * Nq * Kn * 10)
#define OFF_IDX   (OFF_ORF + SZ_ORF)
#define SZ_IDX    (Bq * Nq * Kn)

// ---- attn kernel shared layout (32-bit words) ----
#define PS_FB   132            // feat_b row stride in uint32 (128 pairs + 4 pad)
#define SMA_FEAT 0
#define SMA_ORF  (SMA_FEAT + 64 * PS_FB)    // 8448
#define SMA_RELW (SMA_ORF + PPB * 160)      // 9088
#define SMA_RELB (SMA_RELW + 10 * CRc)      // 10368
#define SMA_IDX  (SMA_RELB + CRc)           // 10496
#define SMA_TOT  (SMA_IDX + 64)             // 10560 words = 42240 B (static smem)

// ---- gemm kernel ----
#define GM_TILE  32            // points per gemm block
#define GK       (Dd + CINc)   // 384
#define PS_A     388           // As row stride (floats): 384 + 4 pad
#define GSM_BYTES (GM_TILE * PS_A * 4)   // 49664 B (dynamic smem)

// Device globals (no allocation allowed)
__device__ float d_relWf[10 * CRc];
__device__ float d_relB[CRc];
__device__ float d_biasC[COUTc];
// attn_W in bf16 m16n8k16 B-fragment layout:
// e = ((nch*16 + s)*4 + j2)*32 + lane ; uint4 = {b0(j),b1(j),b0(j+1),b1(j+1)}
__device__ uint4 d_attnFrag[4 * 16 * 4 * 32];        // 8192 * 16B = 128 KB
// [outWf ; scWf] (BN-folded) in tf32 m16n8k8 B-fragment layout:
// e = (s*16 + j2)*32 + lane ; s: 48 k8-steps, j2: 16 n16-pairs
__device__ uint4 d_wFrag[48 * 16 * 32];              // 24576 * 16B = 384 KB
// pooled scratch [NPTS][256]
__device__ float d_pooled[(size_t)NPTS * Dd];        // 16.8 MB

__device__ __forceinline__ uint32_t to_tf32(float x) {
    uint32_t r;
    asm("cvt.rna.tf32.f32 %0, %1;" : "=r"(r) : "f"(x));
    return r;
}
__device__ __forceinline__ float to_tf32f(float x) {
    return __uint_as_float(to_tf32(x));
}
__device__ __forceinline__ uint32_t pack_bf2(float lo, float hi) {
    __nv_bfloat162 h = __floats2bfloat162_rn(lo, hi);
    return *reinterpret_cast<uint32_t*>(&h);
}

// folded weight for the combined [outW;scW] GEMM
__device__ __forceinline__ float wc_fold(int k, int n,
    const float* out_W, const float* out_g, const float* out_v,
    const float* sc_W,  const float* sc_g,  const float* sc_v)
{
    if (k < Dd)  return out_W[k * COUTc + n] * out_g[n] * rsqrtf(out_v[n] + EPSc);
    return sc_W[(k - Dd) * COUTc + n] * sc_g[n] * rsqrtf(sc_v[n] + EPSc);
}

// ---------------------------------------------------------------------------
// Setup: fold BN, build fragment tables, passthrough copies.
// ---------------------------------------------------------------------------
__global__ void fuse_and_copy_kernel(
    const float* __restrict__ rel_W, const float* __restrict__ rel_b,
    const float* __restrict__ rel_g, const float* __restrict__ rel_be,
    const float* __restrict__ rel_m, const float* __restrict__ rel_v,
    const float* __restrict__ out_W, const float* __restrict__ out_b,
    const float* __restrict__ out_g, const float* __restrict__ out_be,
    const float* __restrict__ out_m, const float* __restrict__ out_v,
    const float* __restrict__ sc_W,  const float* __restrict__ sc_b,
    const float* __restrict__ sc_g,  const float* __restrict__ sc_be,
    const float* __restrict__ sc_m,  const float* __restrict__ sc_v,
    const float* __restrict__ attn_W,
    const float* __restrict__ xyz,   const float* __restrict__ orf,
    const int*   __restrict__ nidx,  float* __restrict__ out)
{
    int t0 = blockIdx.x * blockDim.x + threadIdx.x;
    int stride = gridDim.x * blockDim.x;

    for (int i = t0; i < 10 * CRc; i += stride) {
        int c = i & (CRc - 1);
        d_relWf[i] = rel_W[i] * rel_g[c] * rsqrtf(rel_v[c] + EPSc);
    }
    for (int i = t0; i < CRc; i += stride) {
        float A = rel_g[i] * rsqrtf(rel_v[i] + EPSc);
        d_relB[i] = (rel_b[i] - rel_m[i]) * A + rel_be[i];
    }
    for (int i = t0; i < COUTc; i += stride) {
        float Ao = out_g[i] * rsqrtf(out_v[i] + EPSc);
        float As = sc_g[i] * rsqrtf(sc_v[i] + EPSc);
        d_biasC[i] = (out_b[i] - out_m[i]) * Ao + out_be[i]
                   + (sc_b[i] - sc_m[i]) * As + sc_be[i];
    }

    // attn bf16 fragment table
    for (int e = t0; e < 4 * 16 * 4 * 32; e += stride) {
        int lane = e & 31, j2 = (e >> 5) & 3, s = (e >> 7) & 15, nch = e >> 11;
        int g = lane >> 2, tt = lane & 3, k0 = s * 16;
        int n0 = nch * 64 + (2 * j2) * 8 + g;
        int n1 = n0 + 8;
        uint4 v;
        v.x = pack_bf2(attn_W[(k0 + 2*tt)     * Dd + n0], attn_W[(k0 + 2*tt + 1) * Dd + n0]);
        v.y = pack_bf2(attn_W[(k0 + 2*tt + 8) * Dd + n0], attn_W[(k0 + 2*tt + 9) * Dd + n0]);
        v.z = pack_bf2(attn_W[(k0 + 2*tt)     * Dd + n1], attn_W[(k0 + 2*tt + 1) * Dd + n1]);
        v.w = pack_bf2(attn_W[(k0 + 2*tt + 8) * Dd + n1], attn_W[(k0 + 2*tt + 9) * Dd + n1]);
        d_attnFrag[e] = v;
    }

    // combined [outW;scW] tf32 fragment table
    for (int e = t0; e < 48 * 16 * 32; e += stride) {
        int lane = e & 31, j2 = (e >> 5) & 15, s = e >> 9;   // s 0..47
        int g = lane >> 2, tt = lane & 3, k0 = s * 8;
        int n0 = (2 * j2) * 8 + g;
        int n1 = n0 + 8;
        uint4 v;
        v.x = to_tf32(wc_fold(k0 + tt,     n0, out_W, out_g, out_v, sc_W, sc_g, sc_v));
        v.y = to_tf32(wc_fold(k0 + tt + 4, n0, out_W, out_g, out_v, sc_W, sc_g, sc_v));
        v.z = to_tf32(wc_fold(k0 + tt,     n1, out_W, out_g, out_v, sc_W, sc_g, sc_v));
        v.w = to_tf32(wc_fold(k0 + tt + 4, n1, out_W, out_g, out_v, sc_W, sc_g, sc_v));
        d_wFrag[e] = v;
    }

    // Passthrough copies
    const float4* xs = (const float4*)xyz;
    float4* xd = (float4*)(out + OFF_XYZ);
    for (int i = t0; i < SZ_XYZ / 4; i += stride) xd[i] = xs[i];
    const float4* os = (const float4*)orf;
    float4* od = (float4*)(out + OFF_ORF);
    for (int i = t0; i < SZ_ORF / 4; i += stride) od[i] = os[i];
    float* id = out + OFF_IDX;
    for (int i = t0; i < SZ_IDX; i += stride) id[i] = (float)nidx[i];
}

// ---------------------------------------------------------------------------
// Attention kernel: 4 points/block, 128 threads (warp w == point w), bf16 MMA.
// launch_bounds(128,5): 5 blocks/SM (smem 42.2KB*5=211KB), reg cap 102.
// ---------------------------------------------------------------------------
__global__ __launch_bounds__(NTHR, 5)
void lfa_attn_kernel(const float* __restrict__ feature,
                     const float* __restrict__ orf,
                     const int*   __restrict__ nidx)
{
    __shared__ uint32_t smem[SMA_TOT];
    uint32_t* feat_b = smem + SMA_FEAT;           // [64][PS_FB] bf16x2
    float* orf_s  = (float*)(smem + SMA_ORF);     // [4][160]
    float* relW_s = (float*)(smem + SMA_RELW);    // [10][128]
    float* relB_s = (float*)(smem + SMA_RELB);    // [128]
    int*   idx_s  = (int*)(smem + SMA_IDX);       // [64]

    const int tid = threadIdx.x;
    const int p0  = blockIdx.x * PPB;
    const int b   = p0 >> 13;

    // ---- Stage small data + rel weights ----
    if (tid < 64) idx_s[tid] = nidx[p0 * Kn + tid];
    for (int i = tid; i < PPB * 160; i += NTHR) orf_s[i] = orf[(size_t)p0 * 160 + i];
    for (int i = tid; i < 10 * CRc; i += NTHR) relW_s[i] = d_relWf[i];
    if (tid < CRc) relB_s[tid] = d_relB[tid];
    __syncthreads();

    // ---- Gather neighbor features -> bf16 pairs ----
    const float* fbase = feature + (size_t)b * Nq * CINc;
    for (int i = tid; i < 64 * 32; i += NTHR) {
        int r = i >> 5, c4 = i & 31;
        float4 v = *((const float4*)(fbase + (size_t)idx_s[r] * CINc) + c4);
        uint2 pk;
        pk.x = pack_bf2(v.x, v.y);
        pk.y = pack_bf2(v.z, v.w);
        *(uint2*)&feat_b[r * PS_FB + c4 * 2] = pk;
    }
    // ---- rel MLP (BN folded) -> bf16 pairs at cols 128..255 ----
    for (int i = tid; i < 64 * 64; i += NTHR) {
        int r = i >> 6, c2 = i & 63;
        float a0 = relB_s[2 * c2], a1 = relB_s[2 * c2 + 1];
        const float* o = &orf_s[(r >> 4) * 160 + (r & 15) * 10];
        #pragma unroll
        for (int d = 0; d < 10; d++) {
            float od = o[d];
            a0 += od * relW_s[d * CRc + 2 * c2];
            a1 += od * relW_s[d * CRc + 2 * c2 + 1];
        }
        a0 = (a0 >= 0.f) ? a0 : NEGc * a0;
        a1 = (a1 >= 0.f) ? a1 : NEGc * a1;
        feat_b[r * PS_FB + 64 + c2] = pack_bf2(a0, a1);
    }
    __syncthreads();

    const int w    = tid >> 5;
    const int lane = tid & 31;
    const int g    = lane >> 2;
    const int t    = lane & 3;
    const int arow0 = (w * 16 + g) * PS_FB;
    const int arow8 = arow0 + 8 * PS_FB;
    float* poolrow = d_pooled + (size_t)(p0 + w) * Dd;

    // ---- Logits (bf16 m16n8k16) + softmax + pooling, barrier-free ----
    #pragma unroll 1
    for (int nch = 0; nch < 4; nch++) {
        float acc[8][4];
        #pragma unroll
        for (int j = 0; j < 8; j++) {
            acc[j][0] = 0.f; acc[j][1] = 0.f; acc[j][2] = 0.f; acc[j][3] = 0.f;
        }

        const uint4* bfrag = d_attnFrag + (size_t)(nch * 16) * 128 + lane;

        #pragma unroll
        for (int s = 0; s < 16; s++) {
            const int pc = s * 8;     // packed-pair col base (k0 = 16s)
            uint32_t a0 = feat_b[arow0 + pc + t];
            uint32_t a1 = feat_b[arow8 + pc + t];
            uint32_t a2 = feat_b[arow0 + pc + t + 4];
            uint32_t a3 = feat_b[arow8 + pc + t + 4];
            const uint4* bs = bfrag + s * 128;
            #pragma unroll
            for (int j2 = 0; j2 < 4; j2++) {
                uint4 bv = bs[j2 * 32];
                asm volatile(
                    "mma.sync.aligned.m16n8k16.row.col.f32.bf16.bf16.f32 "
                    "{%0,%1,%2,%3}, {%4,%5,%6,%7}, {%8,%9}, {%0,%1,%2,%3};"
                    : "+f"(acc[2*j2][0]), "+f"(acc[2*j2][1]),
                      "+f"(acc[2*j2][2]), "+f"(acc[2*j2][3])
                    : "r"(a0), "r"(a1), "r"(a2), "r"(a3), "r"(bv.x), "r"(bv.y));
                asm volatile(
                    "mma.sync.aligned.m16n8k16.row.col.f32.bf16.bf16.f32 "
                    "{%0,%1,%2,%3}, {%4,%5,%6,%7}, {%8,%9}, {%0,%1,%2,%3};"
                    : "+f"(acc[2*j2+1][0]), "+f"(acc[2*j2+1][1]),
                      "+f"(acc[2*j2+1][2]), "+f"(acc[2*j2+1][3])
                    : "r"(a0), "r"(a1), "r"(a2), "r"(a3), "r"(bv.z), "r"(bv.w));
            }
        }

        // Softmax over k (no max-subtract: |logit| << 88) + pooling
        #pragma unroll
        for (int j = 0; j < 8; j++) {
            float e0 = __expf(acc[j][0]);
            float e1 = __expf(acc[j][1]);
            float e2 = __expf(acc[j][2]);
            float e3 = __expf(acc[j][3]);
            float s0 = e0 + e2, s1 = e1 + e3;

            // feat values at (rows g,g+8; cols C,C+1), C = nch*64 + j*8 + 2t
            uint32_t u01 = feat_b[arow0 + nch * 32 + j * 4 + t];
            uint32_t u23 = feat_b[arow8 + nch * 32 + j * 4 + t];
            float2 f01 = __bfloat1622float2(*reinterpret_cast<__nv_bfloat162*>(&u01));
            float2 f23 = __bfloat1622float2(*reinterpret_cast<__nv_bfloat162*>(&u23));
            float pp0 = e0 * f01.x + e2 * f23.x;
            float pp1 = e1 * f01.y + e3 * f23.y;

            #pragma unroll
            for (int d = 4; d <= 16; d <<= 1) {
                s0  += __shfl_xor_sync(0xffffffffu, s0, d);
                s1  += __shfl_xor_sync(0xffffffffu, s1, d);
                pp0 += __shfl_xor_sync(0xffffffffu, pp0, d);
                pp1 += __shfl_xor_sync(0xffffffffu, pp1, d);
            }
            if (g == 0) {
                const int C = nch * 64 + j * 8 + 2 * t;
                poolrow[C]     = pp0 / s0;
                poolrow[C + 1] = pp1 / s1;
            }
        }
    }
}

// ---------------------------------------------------------------------------
// Final GEMM: out = leaky([pooled | feature] @ [outWf;scWf] + bias)
// M=16384, N=256, K=384, tf32 MMA. Block: 32 points, 256 threads (8 warps).
// ---------------------------------------------------------------------------
__global__ __launch_bounds__(256, 3)
void lfa_gemm_kernel(const float* __restrict__ feature,
                     float*       __restrict__ out_feat)
{
    extern __shared__ float As[];      // [32][PS_A]

    const int tid = threadIdx.x;
    const int m0b = blockIdx.x * GM_TILE;

    // ---- Stage A tile: cols 0..255 = pooled, 256..383 = feature ----
    for (int i = tid; i < GM_TILE * 96; i += 256) {
        int row = i / 96, q = i % 96;
        int m = m0b + row;
        float4 v;
        if (q < 64) v = *((const float4*)(d_pooled + (size_t)m * Dd) + q);
        else        v = *((const float4*)(feature + (size_t)m * CINc) + (q - 64));
        v.x = to_tf32f(v.x); v.y = to_tf32f(v.y);
        v.z = to_tf32f(v.z); v.w = to_tf32f(v.w);
        *(float4*)&As[row * PS_A + q * 4] = v;
    }
    __syncthreads();

    const int w    = tid >> 5;
    const int lane = tid & 31;
    const int r    = w >> 2;            // 0..1
    const int cs   = w & 3;             // 0..3
    const int g    = lane >> 2;
    const int t    = lane & 3;
    const int arow0 = (r * 16 + g) * PS_A;
    const int arow8 = arow0 + 8 * PS_A;

    float acc[8][4];
    #pragma unroll
    for (int j = 0; j < 8; j++) {
        acc[j][0] = 0.f; acc[j][1] = 0.f; acc[j][2] = 0.f; acc[j][3] = 0.f;
    }

    const uint4* bfrag = d_wFrag + (size_t)(cs * 4) * 32 + lane;

    #pragma unroll 8
    for (int s = 0; s < 48; s++) {
        const int k0 = s * 8;
        uint32_t a0 = __float_as_uint(As[arow0 + k0 + t]);
        uint32_t a1 = __float_as_uint(As[arow8 + k0 + t]);
        uint32_t a2 = __float_as_uint(As[arow0 + k0 + t + 4]);
        uint32_t a3 = __float_as_uint(As[arow8 + k0 + t + 4]);
        const uint4* bs = bfrag + (size_t)s * 16 * 32;
        #pragma unroll
        for (int j2 = 0; j2 < 4; j2++) {
            uint4 bv = bs[j2 * 32];
            asm volatile(
                "mma.sync.aligned.m16n8k8.row.col.f32.tf32.tf32.f32 "
                "{%0,%1,%2,%3}, {%4,%5,%6,%7}, {%8,%9}, {%0,%1,%2,%3};"
                : "+f"(acc[2*j2][0]), "+f"(acc[2*j2][1]),
                  "+f"(acc[2*j2][2]), "+f"(acc[2*j2][3])
                : "r"(a0), "r"(a1), "r"(a2), "r"(a3), "r"(bv.x), "r"(bv.y));
            asm volatile(
                "mma.sync.aligned.m16n8k8.row.col.f32.tf32.tf32.f32 "
                "{%0,%1,%2,%3}, {%4,%5,%6,%7}, {%8,%9}, {%0,%1,%2,%3};"
                : "+f"(acc[2*j2+1][0]), "+f"(acc[2*j2+1][1]),
                  "+f"(acc[2*j2+1][2]), "+f"(acc[2*j2+1][3])
                : "r"(a0), "r"(a1), "r"(a2), "r"(a3), "r"(bv.z), "r"(bv.w));
        }
    }

    // ---- Epilogue: bias + leaky + store ----
    const int mrow0 = m0b + r * 16 + g;
    #pragma unroll
    for (int j = 0; j < 8; j++) {
        const int n0 = cs * 64 + j * 8 + 2 * t;
        float2 bias = *(const float2*)&d_biasC[n0];
        float o0 = acc[j][0] + bias.x;
        float o1 = acc[j][1] + bias.y;
        float o2 = acc[j][2] + bias.x;
        float o3 = acc[j][3] + bias.y;
        o0 = (o0 >= 0.f) ? o0 : NEGc * o0;
        o1 = (o1 >= 0.f) ? o1 : NEGc * o1;
        o2 = (o2 >= 0.f) ? o2 : NEGc * o2;
        o3 = (o3 >= 0.f) ? o3 : NEGc * o3;
        *(float2*)&out_feat[(size_t)mrow0 * COUTc + n0]       = make_float2(o0, o1);
        *(float2*)&out_feat[(size_t)(mrow0 + 8) * COUTc + n0] = make_float2(o2, o3);
    }
}

// ---------------------------------------------------------------------------
extern "C" void kernel_launch(void* const* d_in, const int* in_sizes, int n_in,
                              void* d_out, int out_size)
{
    const float* xyz     = (const float*)d_in[0];
    const float* feature = (const float*)d_in[1];
    const float* orf     = (const float*)d_in[2];
    const int*   nidx    = (const int*)  d_in[3];
    const float* rel_W   = (const float*)d_in[4];
    const float* rel_b   = (const float*)d_in[5];
    const float* rel_g   = (const float*)d_in[6];
    const float* rel_be  = (const float*)d_in[7];
    const float* rel_m   = (const float*)d_in[8];
    const float* rel_v   = (const float*)d_in[9];
    const float* attn_W  = (const float*)d_in[10];
    const float* out_W   = (const float*)d_in[11];
    const float* out_b   = (const float*)d_in[12];
    const float* out_g   = (const float*)d_in[13];
    const float* out_be  = (const float*)d_in[14];
    const float* out_m   = (const float*)d_in[15];
    const float* out_v   = (const float*)d_in[16];
    const float* sc_W    = (const float*)d_in[17];
    const float* sc_b    = (const float*)d_in[18];
    const float* sc_g    = (const float*)d_in[19];
    const float* sc_be   = (const float*)d_in[20];
    const float* sc_m    = (const float*)d_in[21];
    const float* sc_v    = (const float*)d_in[22];

    float* out = (float*)d_out;

    cudaFuncSetAttribute(lfa_gemm_kernel,
                         cudaFuncAttributeMaxDynamicSharedMemorySize, GSM_BYTES);

    fuse_and_copy_kernel<<<1024, 256>>>(rel_W, rel_b, rel_g, rel_be, rel_m, rel_v,
                                        out_W, out_b, out_g, out_be, out_m, out_v,
                                        sc_W,  sc_b,  sc_g,  sc_be,  sc_m,  sc_v,
                                        attn_W, xyz, orf, nidx, out);

    lfa_attn_kernel<<<NBLK, NTHR>>>(feature, orf, nidx);

    lfa_gemm_kernel<<<NPTS / GM_TILE, 256, GSM_BYTES>>>(feature, out + OFF_OUT);
}